// round 1
// baseline (speedup 1.0000x reference)
#include <cuda_runtime.h>

// LabelClusterLoss: loss over E = X.reshape(C0, T, C1), X = [C0*T, C1] fp32.
// One streaming pass computes Q, A (row-sum squares), Ccol (per-(t,c1) column
// sums over c0); second tiny pass reduces Ccol -> B, TT; third computes loss.

namespace {
constexpr int T  = 128;
constexpr int C0 = 512;
constexpr int C1 = 1024;
constexpr int BLOCKS_PER_T  = 4;
constexpr int ROWS_PER_BLOCK = C0 / BLOCKS_PER_T;   // 128
constexpr int NTHREADS = 256;
constexpr int NWARPS   = NTHREADS / 32;             // 8
constexpr int ROWS_PER_WARP = ROWS_PER_BLOCK / NWARPS; // 16
}

// Scratch (no cudaMalloc allowed): 512 KB column sums + scalar accumulators.
__device__ float  g_ccol[T * C1];
__device__ double g_Q, g_A, g_B, g_TT;

__global__ void lcl_zero() {
    int idx = blockIdx.x * blockDim.x + threadIdx.x;
    if (idx < T * C1) g_ccol[idx] = 0.f;
    if (idx == 0) { g_Q = 0.0; g_A = 0.0; g_B = 0.0; g_TT = 0.0; }
}

__global__ __launch_bounds__(NTHREADS) void lcl_pass1(const float4* __restrict__ X) {
    const int t    = blockIdx.x / BLOCKS_PER_T;
    const int bsub = blockIdx.x % BLOCKS_PER_T;
    const int warp = threadIdx.x >> 5;
    const int lane = threadIdx.x & 31;

    // Lane-local column partials: csum[k*4+j] accumulates column k*128 + lane*4 + j.
    float csum[32];
#pragma unroll
    for (int i = 0; i < 32; i++) csum[i] = 0.f;
    float q = 0.f;   // sum of squares
    float a = 0.f;   // sum of (row sum)^2 (lane 0 only)

    const int c0_base = bsub * ROWS_PER_BLOCK + warp * ROWS_PER_WARP;

    for (int r = 0; r < ROWS_PER_WARP; r++) {
        const int c0 = c0_base + r;
        const float4* p = X + (size_t)(c0 * T + t) * (C1 / 4) + lane;
        float rs = 0.f;
#pragma unroll
        for (int k = 0; k < 8; k++) {
            float4 v = p[k * 32];                 // cols k*128 + lane*4 .. +3
            q  += v.x * v.x + v.y * v.y + v.z * v.z + v.w * v.w;
            rs += v.x + v.y + v.z + v.w;
            csum[k * 4 + 0] += v.x;
            csum[k * 4 + 1] += v.y;
            csum[k * 4 + 2] += v.z;
            csum[k * 4 + 3] += v.w;
        }
#pragma unroll
        for (int o = 16; o; o >>= 1) rs += __shfl_xor_sync(0xffffffffu, rs, o);
        if (lane == 0) a += rs * rs;              // full row sum of 1024 cols
    }

    // Cross-warp column-sum reduction in shared, then RED to global scratch.
    __shared__ float scol[C1];
    for (int i = threadIdx.x; i < C1; i += NTHREADS) scol[i] = 0.f;
    __syncthreads();
#pragma unroll
    for (int k = 0; k < 8; k++) {
#pragma unroll
        for (int j = 0; j < 4; j++)
            atomicAdd(&scol[k * 128 + lane * 4 + j], csum[k * 4 + j]);
    }
    __syncthreads();
    for (int i = threadIdx.x; i < C1; i += NTHREADS)
        atomicAdd(&g_ccol[t * C1 + i], scol[i]);

    // Block-reduce scalars, then double atomics (precision headroom).
#pragma unroll
    for (int o = 16; o; o >>= 1) q += __shfl_xor_sync(0xffffffffu, q, o);
    __shared__ float sq[NWARPS], sa[NWARPS];
    if (lane == 0) { sq[warp] = q; sa[warp] = a; }
    __syncthreads();
    if (threadIdx.x == 0) {
        double tq = 0.0, ta = 0.0;
        for (int w = 0; w < NWARPS; w++) { tq += (double)sq[w]; ta += (double)sa[w]; }
        atomicAdd(&g_Q, tq);
        atomicAdd(&g_A, ta);
    }
}

__global__ __launch_bounds__(256) void lcl_pass2() {
    const int t = blockIdx.x;          // one block per t
    const int warp = threadIdx.x >> 5;
    const int lane = threadIdx.x & 31;
    float s = 0.f, ss = 0.f;
    for (int j = threadIdx.x; j < C1; j += 256) {
        float v = g_ccol[t * C1 + j];
        s  += v;
        ss += v * v;
    }
#pragma unroll
    for (int o = 16; o; o >>= 1) {
        s  += __shfl_xor_sync(0xffffffffu, s,  o);
        ss += __shfl_xor_sync(0xffffffffu, ss, o);
    }
    __shared__ float as[8], ass[8];
    if (lane == 0) { as[warp] = s; ass[warp] = ss; }
    __syncthreads();
    if (threadIdx.x == 0) {
        double ts = 0.0, tss = 0.0;
        for (int w = 0; w < 8; w++) { ts += (double)as[w]; tss += (double)ass[w]; }
        atomicAdd(&g_B, tss);
        atomicAdd(&g_TT, ts * ts);     // Tsum[t]^2
    }
}

__global__ void lcl_finish(float* __restrict__ out) {
    const double Q = g_Q, A = g_A, B = g_B, TT = g_TT;
    const double c0 = (double)C0, c1 = (double)C1;
    const double cross = TT / (c0 * c1);
    const double intra      = Q - A / c1;
    const double inter      = A / c1 - cross;
    const double dual_intra = Q - B / c0;
    const double dual_inter = B / c0 - cross;
    const double loss = 0.5 * (intra / inter + dual_intra / dual_inter) / (c0 * c1);
    out[0] = (float)loss;
}

extern "C" void kernel_launch(void* const* d_in, const int* in_sizes, int n_in,
                              void* d_out, int out_size) {
    (void)in_sizes; (void)n_in; (void)out_size;
    const float4* X = (const float4*)d_in[0];
    float* out = (float*)d_out;

    lcl_zero<<<(T * C1 + 255) / 256, 256>>>();
    lcl_pass1<<<T * BLOCKS_PER_T, NTHREADS>>>(X);
    lcl_pass2<<<T, 256>>>();
    lcl_finish<<<1, 1>>>(out);
}

// round 4
// speedup vs baseline: 1.1709x; 1.1709x over previous
#include <cuda_runtime.h>

// LabelClusterLoss: loss over E = X.reshape(C0, T, C1), X = [C0*T, C1] fp32.
// Sufficient statistics in one streaming pass:
//   Q  = sum x^2
//   A  = sum over (c0,t) of (row-sum over c1)^2
//   colsum[t][c1] = sum over c0            -> B = sum colsum^2, Tsum[t] = sum_j colsum
//   TT = sum_t Tsum[t]^2
// loss = 0.5*((Q - A/C1)/(A/C1 - TT/(C0*C1)) + (Q - B/C0)/(B/C0 - TT/(C0*C1)))/(C0*C1)

namespace {
constexpr int T  = 128;
constexpr int C0 = 512;
constexpr int C1 = 1024;
constexpr int BLOCKS_PER_T   = 4;
constexpr int ROWS_PER_BLOCK = C0 / BLOCKS_PER_T;       // 128
constexpr int NTHREADS = 256;
constexpr int NWARPS   = NTHREADS / 32;                 // 8
constexpr int ROWS_PER_WARP = ROWS_PER_BLOCK / NWARPS;  // 16
constexpr int NBLK1 = T * BLOCKS_PER_T;                 // 512
}

// Scratch (no cudaMalloc allowed). Plain stores only -> no zeroing pass.
__device__ float g_colpart[NBLK1 * C1];   // [t][bsub][C1]  (2 MB)
__device__ float g_qpart[NBLK1];
__device__ float g_apart[NBLK1];
__device__ float g_Bpart[T];
__device__ float g_Tsum[T];

__global__ __launch_bounds__(NTHREADS) void lcl_pass1(const float4* __restrict__ X) {
    const int t    = blockIdx.x / BLOCKS_PER_T;
    const int bsub = blockIdx.x % BLOCKS_PER_T;
    const int warp = threadIdx.x >> 5;
    const int lane = threadIdx.x & 31;

    // Lane-local column partials: csum[k*4+j] is column k*128 + lane*4 + j.
    float csum[32];
#pragma unroll
    for (int i = 0; i < 32; i++) csum[i] = 0.f;
    float rpart[ROWS_PER_WARP];          // per-lane partial row sums (deferred reduce)
    float q = 0.f;

    const int c0_base = bsub * ROWS_PER_BLOCK + warp * ROWS_PER_WARP;

#pragma unroll 2
    for (int r = 0; r < ROWS_PER_WARP; r++) {
        const int c0 = c0_base + r;
        const float4* p = X + (size_t)(c0 * T + t) * (C1 / 4) + lane;
        float rs = 0.f;
#pragma unroll
        for (int k = 0; k < 8; k++) {
            const float4 v = __ldcs(&p[k * 32]);      // cols k*128 + lane*4 .. +3
            q  += v.x * v.x + v.y * v.y + v.z * v.z + v.w * v.w;
            rs += v.x + v.y + v.z + v.w;
            csum[k * 4 + 0] += v.x;
            csum[k * 4 + 1] += v.y;
            csum[k * 4 + 2] += v.z;
            csum[k * 4 + 3] += v.w;
        }
        rpart[r] = rs;
    }

    // Deferred row-sum reductions (outside the load stream). After the
    // butterfly every lane holds the full row sum; accumulate a identically
    // per lane and read lane 0's copy below (NO cross-lane sum of a).
    float a = 0.f;
#pragma unroll
    for (int r = 0; r < ROWS_PER_WARP; r++) {
        float rs = rpart[r];
#pragma unroll
        for (int o = 16; o; o >>= 1) rs += __shfl_xor_sync(0xffffffffu, rs, o);
        a += rs * rs;
    }

    // Cross-warp column reduction in shared (8 adds per address), then one
    // coalesced STG of this block's 1024 column partials.
    __shared__ float scol[C1];
    for (int i = threadIdx.x; i < C1; i += NTHREADS) scol[i] = 0.f;
    __syncthreads();
#pragma unroll
    for (int k = 0; k < 8; k++)
#pragma unroll
        for (int j = 0; j < 4; j++)
            atomicAdd(&scol[k * 128 + lane * 4 + j], csum[k * 4 + j]);
    __syncthreads();
    float* dst = g_colpart + (size_t)blockIdx.x * C1;
    for (int i = threadIdx.x; i < C1; i += NTHREADS) dst[i] = scol[i];

    // Block-reduce q and a; plain store per block.
#pragma unroll
    for (int o = 16; o; o >>= 1) q += __shfl_xor_sync(0xffffffffu, q, o);
    __shared__ float sq[NWARPS], sa[NWARPS];
    if (lane == 0) { sq[warp] = q; sa[warp] = a; }
    __syncthreads();
    if (threadIdx.x == 0) {
        float tq = 0.f, ta = 0.f;
#pragma unroll
        for (int w = 0; w < NWARPS; w++) { tq += sq[w]; ta += sa[w]; }
        g_qpart[blockIdx.x] = tq;
        g_apart[blockIdx.x] = ta;
    }
}

__global__ __launch_bounds__(256) void lcl_pass2() {
    const int t    = blockIdx.x;     // one block per t
    const int warp = threadIdx.x >> 5;
    const int lane = threadIdx.x & 31;
    const float* base = g_colpart + (size_t)t * BLOCKS_PER_T * C1;
    float s = 0.f, ss = 0.f;
    for (int j = threadIdx.x; j < C1; j += 256) {
        float v = base[j] + base[C1 + j] + base[2 * C1 + j] + base[3 * C1 + j];
        s  += v;
        ss += v * v;
    }
#pragma unroll
    for (int o = 16; o; o >>= 1) {
        s  += __shfl_xor_sync(0xffffffffu, s,  o);
        ss += __shfl_xor_sync(0xffffffffu, ss, o);
    }
    __shared__ float as[8], ass[8];
    if (lane == 0) { as[warp] = s; ass[warp] = ss; }
    __syncthreads();
    if (threadIdx.x == 0) {
        float ts = 0.f, tss = 0.f;
#pragma unroll
        for (int w = 0; w < 8; w++) { ts += as[w]; tss += ass[w]; }
        g_Bpart[t] = tss;
        g_Tsum[t]  = ts;
    }
}

__global__ __launch_bounds__(512) void lcl_finish(float* __restrict__ out) {
    const int tid = threadIdx.x;
    double q = 0.0, a = 0.0, b = 0.0, tt = 0.0;
    if (tid < NBLK1) { q = (double)g_qpart[tid]; a = (double)g_apart[tid]; }
    if (tid < T) {
        b = (double)g_Bpart[tid];
        double ts = (double)g_Tsum[tid];
        tt = ts * ts;
    }
    __shared__ double sq[512], sa[512], sb[512], st[512];
    sq[tid] = q; sa[tid] = a; sb[tid] = b; st[tid] = tt;
    __syncthreads();
    for (int o = 256; o; o >>= 1) {
        if (tid < o) {
            sq[tid] += sq[tid + o];
            sa[tid] += sa[tid + o];
            sb[tid] += sb[tid + o];
            st[tid] += st[tid + o];
        }
        __syncthreads();
    }
    if (tid == 0) {
        const double Q = sq[0], A = sa[0], B = sb[0], TT = st[0];
        const double c0 = (double)C0, c1 = (double)C1;
        const double cross = TT / (c0 * c1);
        const double intra      = Q - A / c1;
        const double inter      = A / c1 - cross;
        const double dual_intra = Q - B / c0;
        const double dual_inter = B / c0 - cross;
        out[0] = (float)(0.5 * (intra / inter + dual_intra / dual_inter) / (c0 * c1));
    }
}

extern "C" void kernel_launch(void* const* d_in, const int* in_sizes, int n_in,
                              void* d_out, int out_size) {
    (void)in_sizes; (void)n_in; (void)out_size;
    const float4* X = (const float4*)d_in[0];
    float* out = (float*)d_out;

    lcl_pass1<<<NBLK1, NTHREADS>>>(X);
    lcl_pass2<<<T, 256>>>();
    lcl_finish<<<1, 512>>>(out);
}